// round 2
// baseline (speedup 1.0000x reference)
#include <cuda_runtime.h>
#include <cuda_fp16.h>
#include <cstdint>

// ============================================================================
// GptOssMoEExperts: router collapses to identity (softmax over top-k sums to 1
// and the expert MLP is shared), so
//   out = ((x@Wg^T+bg) * silu(x@Wu^T+bu)) @ W2^T + b2
// Two fp16 mma.sync GEMMs with cp.async pipelines + fused SiLU epilogue.
// (tcgen05 is unusable: harness compiles via compute_103 virtual arch, which
//  rejects sm_103a-only PTX. mma.sync/ldmatrix/cp.async are baseline.)
// ============================================================================

#define SEQ   4096
#define HID   2880
#define INTER 2880

static constexpr int BM     = 128;
static constexpr int BK     = 64;            // fp16 elems -> 128B rows (8 x 16B units)
static constexpr int KIT    = HID / BK;      // 45
static constexpr int STAGES = 3;

// ---------------------------------------------------------------------------
// Scratch (__device__ globals = sanctioned allocation-free scratch)
// ---------------------------------------------------------------------------
__device__ __align__(128) __half g_xh [(size_t)SEQ * HID];
__device__ __align__(128) __half g_w1h[(size_t)2 * INTER * HID];
__device__ __align__(128) __half g_w2h[(size_t)HID * INTER];
__device__ __align__(128) __half g_hh [(size_t)SEQ * INTER];

// ---------------------------------------------------------------------------
// PTX helpers
// ---------------------------------------------------------------------------
__device__ __forceinline__ uint32_t smem_u32(const void* p) {
    uint32_t a;
    asm("{ .reg .u64 t; cvta.to.shared.u64 t, %1; cvt.u32.u64 %0, t; }" : "=r"(a) : "l"(p));
    return a;
}

__device__ __forceinline__ void ldsm4(uint32_t* r, uint32_t a) {
    asm volatile("ldmatrix.sync.aligned.m8n8.x4.shared.b16 {%0,%1,%2,%3}, [%4];"
                 : "=r"(r[0]), "=r"(r[1]), "=r"(r[2]), "=r"(r[3]) : "r"(a));
}
__device__ __forceinline__ void ldsm2(uint32_t* r, uint32_t a) {
    asm volatile("ldmatrix.sync.aligned.m8n8.x2.shared.b16 {%0,%1}, [%2];"
                 : "=r"(r[0]), "=r"(r[1]) : "r"(a));
}
__device__ __forceinline__ void mma16816(float* d, const uint32_t* a, const uint32_t* b) {
    asm volatile(
        "mma.sync.aligned.m16n8k16.row.col.f32.f16.f16.f32 "
        "{%0,%1,%2,%3}, {%4,%5,%6,%7}, {%8,%9}, {%0,%1,%2,%3};"
        : "+f"(d[0]), "+f"(d[1]), "+f"(d[2]), "+f"(d[3])
        : "r"(a[0]), "r"(a[1]), "r"(a[2]), "r"(a[3]), "r"(b[0]), "r"(b[1]));
}
__device__ __forceinline__ void cp16(uint32_t s, const void* g) {
    asm volatile("cp.async.cg.shared.global [%0], [%1], 16;" :: "r"(s), "l"(g) : "memory");
}
#define CP_COMMIT()  asm volatile("cp.async.commit_group;" ::: "memory")
#define CP_WAIT_1()  asm volatile("cp.async.wait_group 1;"  ::: "memory")

// ---------------------------------------------------------------------------
// fp32 -> fp16 conversion (vectorized)
// ---------------------------------------------------------------------------
__global__ void cvt_kernel(const float4* __restrict__ src, uint2* __restrict__ dst, int n4) {
    int i = blockIdx.x * blockDim.x + threadIdx.x;
    if (i >= n4) return;
    float4 v = src[i];
    __half2 a = __floats2half2_rn(v.x, v.y);
    __half2 b = __floats2half2_rn(v.z, v.w);
    uint2 o;
    o.x = *reinterpret_cast<uint32_t*>(&a);
    o.y = *reinterpret_cast<uint32_t*>(&b);
    dst[i] = o;
}

// ---------------------------------------------------------------------------
// Pipelined fp16 GEMM:  C[BM x BN] += A[BM x K] * B[BN x K]^T
//   FUSED=true : B holds gate rows [n] and up rows [INTER+n];
//                epilogue h = (Cg+bg)*silu(Cu+bu) -> fp16 outH
//   FUSED=false: epilogue out = C + bias -> fp32 outF
// 512 threads = 16 warps in a 4(M) x 4(N) grid; warp tile 32 x (BN/4).
// Smem rows are 128B; 16B units are XOR-swizzled by (row&7) -> conflict-free
// for both cp.async stores and ldmatrix reads.
// ---------------------------------------------------------------------------
template <bool FUSED, int BN>
__global__ void __launch_bounds__(512, 1)
gemm_f16(const __half* __restrict__ A, const __half* __restrict__ B,
         const float* __restrict__ bias,
         __half* __restrict__ outH, float* __restrict__ outF) {
    constexpr int WN      = BN / 4;                       // 24 or 48
    constexpr int NF      = WN / 8;                       // n8 frags/warp: 3 or 6
    constexpr int OFF_B   = BM * 128;                     // A tile bytes (16384)
    constexpr int B_BYTES = BN * 128;
    constexpr int STAGE   = OFF_B + B_BYTES * (FUSED ? 2 : 1);

    extern __shared__ __align__(128) char smem[];
    const uint32_t sb0 = smem_u32(smem);
    const int tid = threadIdx.x;
    const int l   = tid & 31;
    const int wid = tid >> 5;
    const int wm  = wid >> 2;
    const int wn  = wid & 3;
    const int mBase = blockIdx.x * BM;
    const int nBase = blockIdx.y * BN;

    auto load_stage = [&](int kt, int slot) {
        const uint32_t sb = sb0 + slot * STAGE;
        const int kc = kt * BK;
        // A tile: 128 rows x 8 units = 1024 chunks
        #pragma unroll
        for (int k = 0; k < 2; k++) {
            int idx = tid + k * 512;
            int row = idx >> 3, u = idx & 7;
            cp16(sb + row * 128 + ((u ^ (row & 7)) << 4),
                 A + (size_t)(mBase + row) * HID + kc + u * 8);
        }
        // B tile(s): BN rows x 8 units
        #pragma unroll
        for (int idx = tid; idx < BN * 8; idx += 512) {
            int row = idx >> 3, u = idx & 7;
            cp16(sb + OFF_B + row * 128 + ((u ^ (row & 7)) << 4),
                 B + (size_t)(nBase + row) * HID + kc + u * 8);
        }
        if (FUSED) {
            #pragma unroll
            for (int idx = tid; idx < BN * 8; idx += 512) {
                int row = idx >> 3, u = idx & 7;
                cp16(sb + OFF_B + B_BYTES + row * 128 + ((u ^ (row & 7)) << 4),
                     B + (size_t)(INTER + nBase + row) * HID + kc + u * 8);
            }
        }
    };

    float accG[2][NF][4] = {};
    float accU[2][NF][4] = {};   // dead (eliminated) when !FUSED

    // prologue: fill STAGES-1 stages
    #pragma unroll
    for (int s = 0; s < STAGES - 1; s++) {
        load_stage(s, s);
        CP_COMMIT();
    }

    const int l7  = l & 7;
    const int lhi = l >> 4;
    const int le  = l & 15;
    const int aRow0 = wm * 32 + le;

    for (int kt = 0; kt < KIT; kt++) {
        CP_WAIT_1();          // stage kt's group complete (for this thread)
        __syncthreads();      // ... for every thread; also fences stage reuse

        const int nk = kt + STAGES - 1;
        if (nk < KIT) load_stage(nk, nk % STAGES);
        CP_COMMIT();

        const uint32_t sA = sb0 + (kt % STAGES) * STAGE;
        const uint32_t sB = sA + OFF_B;

        #pragma unroll
        for (int ks = 0; ks < 4; ks++) {           // 4 x k16 per BK=64
            uint32_t a[2][4];
            #pragma unroll
            for (int i = 0; i < 2; i++)
                ldsm4(a[i], sA + (uint32_t)(aRow0 + i * 16) * 128 +
                              (uint32_t)(((ks * 2 + lhi) ^ l7) << 4));
            if constexpr (FUSED) {
                uint32_t bg[NF][2], bu[NF][2];
                #pragma unroll
                for (int j = 0; j < NF; j++) {
                    uint32_t row  = wn * WN + j * 8 + l7;
                    uint32_t unit = (uint32_t)((ks * 2 + (le >> 3)) ^ l7);
                    ldsm2(bg[j], sB + row * 128 + (unit << 4));
                    ldsm2(bu[j], sB + B_BYTES + row * 128 + (unit << 4));
                }
                #pragma unroll
                for (int i = 0; i < 2; i++)
                    #pragma unroll
                    for (int j = 0; j < NF; j++) {
                        mma16816(accG[i][j], a[i], bg[j]);
                        mma16816(accU[i][j], a[i], bu[j]);
                    }
            } else {
                uint32_t bb[NF / 2][4];
                #pragma unroll
                for (int p = 0; p < NF / 2; p++) {
                    int q = l >> 3;
                    uint32_t row  = wn * WN + p * 16 + ((q >> 1) << 3) + l7;
                    uint32_t unit = (uint32_t)((ks * 2 + (q & 1)) ^ l7);
                    ldsm4(bb[p], sB + row * 128 + (unit << 4));
                }
                #pragma unroll
                for (int i = 0; i < 2; i++)
                    #pragma unroll
                    for (int p = 0; p < NF / 2; p++) {
                        mma16816(accG[i][2 * p],     a[i], &bb[p][0]);
                        mma16816(accG[i][2 * p + 1], a[i], &bb[p][2]);
                    }
            }
        }
    }

    // ------------------------------- epilogue -------------------------------
    const int r00 = mBase + wm * 32 + (l >> 2);
    const int cB  = nBase + wn * WN + 2 * (l & 3);

    if constexpr (FUSED) {
        #pragma unroll
        for (int i = 0; i < 2; i++)
            #pragma unroll
            for (int j = 0; j < NF; j++) {
                const int c = cB + j * 8;
                const float bg0 = bias[c],         bg1 = bias[c + 1];
                const float bu0 = bias[INTER + c], bu1 = bias[INTER + c + 1];
                #pragma unroll
                for (int hh = 0; hh < 2; hh++) {
                    const int r = r00 + i * 16 + hh * 8;
                    float g0 = accG[i][j][2 * hh]     + bg0;
                    float g1 = accG[i][j][2 * hh + 1] + bg1;
                    float u0 = accU[i][j][2 * hh]     + bu0;
                    float u1 = accU[i][j][2 * hh + 1] + bu1;
                    float h0 = g0 * u0 * (1.0f / (1.0f + __expf(-u0)));
                    float h1 = g1 * u1 * (1.0f / (1.0f + __expf(-u1)));
                    *reinterpret_cast<__half2*>(outH + (size_t)r * INTER + c) =
                        __floats2half2_rn(h0, h1);
                }
            }
    } else {
        #pragma unroll
        for (int i = 0; i < 2; i++)
            #pragma unroll
            for (int j = 0; j < NF; j++) {
                const int c = cB + j * 8;
                const float b0 = bias[c], b1 = bias[c + 1];
                #pragma unroll
                for (int hh = 0; hh < 2; hh++) {
                    const int r = r00 + i * 16 + hh * 8;
                    float2 v;
                    v.x = accG[i][j][2 * hh]     + b0;
                    v.y = accG[i][j][2 * hh + 1] + b1;
                    *reinterpret_cast<float2*>(outF + (size_t)r * HID + c) = v;
                }
            }
    }
}

// ---------------------------------------------------------------------------
// Host
// ---------------------------------------------------------------------------
extern "C" void kernel_launch(void* const* d_in, const int* in_sizes, int n_in,
                              void* d_out, int out_size) {
    const float* x  = (const float*)d_in[0];   // hidden_states (4096, 2880)
    const float* w1 = (const float*)d_in[3];   // gate_up_w (5760, 2880)
    const float* b1 = (const float*)d_in[4];   // gate_up_b (5760,)
    const float* w2 = (const float*)d_in[5];   // down_w (2880, 2880)
    const float* b2 = (const float*)d_in[6];   // down_b (2880,)
    float* out = (float*)d_out;                // (4096, 2880) fp32

    void *px, *pw1, *pw2, *ph;
    cudaGetSymbolAddress(&px,  g_xh);
    cudaGetSymbolAddress(&pw1, g_w1h);
    cudaGetSymbolAddress(&pw2, g_w2h);
    cudaGetSymbolAddress(&ph,  g_hh);

    // fp32 -> fp16
    {
        int n4 = (SEQ * HID) / 4;
        cvt_kernel<<<(n4 + 255) / 256, 256>>>((const float4*)x,  (uint2*)px,  n4);
        n4 = (2 * INTER * HID) / 4;
        cvt_kernel<<<(n4 + 255) / 256, 256>>>((const float4*)w1, (uint2*)pw1, n4);
        n4 = (HID * INTER) / 4;
        cvt_kernel<<<(n4 + 255) / 256, 256>>>((const float4*)w2, (uint2*)pw2, n4);
    }

    constexpr int SM1 = STAGES * (BM * 128 + 2 * 96 * 128);   // 122880
    constexpr int SM2 = STAGES * (BM * 128 + 192 * 128);      // 122880
    cudaFuncSetAttribute(gemm_f16<true, 96>,
                         cudaFuncAttributeMaxDynamicSharedMemorySize, SM1);
    cudaFuncSetAttribute(gemm_f16<false, 192>,
                         cudaFuncAttributeMaxDynamicSharedMemorySize, SM2);

    // GEMM1: h = (x@Wg^T+bg) * silu(x@Wu^T+bu)   (fp16 h)
    gemm_f16<true, 96><<<dim3(SEQ / BM, INTER / 96), 512, SM1>>>(
        (const __half*)px, (const __half*)pw1, b1, (__half*)ph, nullptr);
    // GEMM2: out = h@W2^T + b2   (fp32 out)
    gemm_f16<false, 192><<<dim3(SEQ / BM, HID / 192), 512, SM2>>>(
        (const __half*)ph, (const __half*)pw2, b2, nullptr, out);
}

// round 3
// speedup vs baseline: 1.1735x; 1.1735x over previous
#include <cuda_runtime.h>
#include <cuda_fp16.h>
#include <cstdint>

// ============================================================================
// GptOssMoEExperts: router collapses to identity (softmax over top-k sums to 1
// and the expert MLP is shared), so
//   out = ((x@Wg^T+bg) * silu(x@Wu^T+bu)) @ W2^T + b2
// Plan: cvt fp32->fp16, GEMM1 (x @ W1^T + b1 -> gateup fp16, all 5760 cols),
// elementwise SiLU (gate * up * sigmoid(up) -> h fp16), GEMM2 (h @ W2^T + b2).
// mma.sync m16n8k16 fp16->fp32, cp.async 3-stage pipeline, register
// double-buffered fragments, 256 thr/CTA x 2 CTA/SM.
// ============================================================================

#define SEQ   4096
#define HID   2880
#define INTER 2880
#define NGU   (2 * INTER)   // 5760

static constexpr int BM     = 128;
static constexpr int BN     = 96;
static constexpr int BK     = 64;            // fp16 elems -> 128B rows
static constexpr int KIT    = HID / BK;      // 45
static constexpr int STAGES = 3;
static constexpr int OFF_B  = BM * 128;               // 16384
static constexpr int STAGE  = OFF_B + BN * 128;       // 28672
static constexpr int SMEM_SZ = STAGES * STAGE;        // 86016

// ---------------------------------------------------------------------------
// Scratch (__device__ globals = sanctioned allocation-free scratch)
// ---------------------------------------------------------------------------
__device__ __align__(128) __half g_xh [(size_t)SEQ * HID];
__device__ __align__(128) __half g_w1h[(size_t)NGU * HID];
__device__ __align__(128) __half g_w2h[(size_t)HID * INTER];
__device__ __align__(128) __half g_gu [(size_t)SEQ * NGU];
__device__ __align__(128) __half g_hh [(size_t)SEQ * INTER];

// ---------------------------------------------------------------------------
// PTX helpers
// ---------------------------------------------------------------------------
__device__ __forceinline__ uint32_t smem_u32(const void* p) {
    uint32_t a;
    asm("{ .reg .u64 t; cvta.to.shared.u64 t, %1; cvt.u32.u64 %0, t; }" : "=r"(a) : "l"(p));
    return a;
}
__device__ __forceinline__ void ldsm4(uint32_t* r, uint32_t a) {
    asm volatile("ldmatrix.sync.aligned.m8n8.x4.shared.b16 {%0,%1,%2,%3}, [%4];"
                 : "=r"(r[0]), "=r"(r[1]), "=r"(r[2]), "=r"(r[3]) : "r"(a));
}
__device__ __forceinline__ void mma16816(float* d, const uint32_t* a, const uint32_t* b) {
    asm volatile(
        "mma.sync.aligned.m16n8k16.row.col.f32.f16.f16.f32 "
        "{%0,%1,%2,%3}, {%4,%5,%6,%7}, {%8,%9}, {%0,%1,%2,%3};"
        : "+f"(d[0]), "+f"(d[1]), "+f"(d[2]), "+f"(d[3])
        : "r"(a[0]), "r"(a[1]), "r"(a[2]), "r"(a[3]), "r"(b[0]), "r"(b[1]));
}
__device__ __forceinline__ void cp16(uint32_t s, const void* g) {
    asm volatile("cp.async.cg.shared.global [%0], [%1], 16;" :: "r"(s), "l"(g) : "memory");
}
#define CP_COMMIT()  asm volatile("cp.async.commit_group;" ::: "memory")
#define CP_WAIT_1()  asm volatile("cp.async.wait_group 1;"  ::: "memory")

// ---------------------------------------------------------------------------
// fp32 -> fp16 conversion (vectorized)
// ---------------------------------------------------------------------------
__global__ void cvt_kernel(const float4* __restrict__ src, uint2* __restrict__ dst, int n4) {
    int i = blockIdx.x * blockDim.x + threadIdx.x;
    if (i >= n4) return;
    float4 v = src[i];
    __half2 a = __floats2half2_rn(v.x, v.y);
    __half2 b = __floats2half2_rn(v.z, v.w);
    uint2 o;
    o.x = *reinterpret_cast<uint32_t*>(&a);
    o.y = *reinterpret_cast<uint32_t*>(&b);
    dst[i] = o;
}

// ---------------------------------------------------------------------------
// Elementwise SiLU-mul: h[r,c] = gu[r,c] * silu(gu[r,INTER+c]), 8 elems/thread
// ---------------------------------------------------------------------------
__global__ void silu_kernel(const __half* __restrict__ gu, __half* __restrict__ h) {
    const int i = blockIdx.x * blockDim.x + threadIdx.x;
    const int n8 = SEQ * INTER / 8;
    if (i >= n8) return;
    const int r  = i / (INTER / 8);
    const int c8 = i % (INTER / 8);
    const uint4 gv = *reinterpret_cast<const uint4*>(gu + (size_t)r * NGU + c8 * 8);
    const uint4 uv = *reinterpret_cast<const uint4*>(gu + (size_t)r * NGU + INTER + c8 * 8);
    const __half2* gp = reinterpret_cast<const __half2*>(&gv);
    const __half2* up = reinterpret_cast<const __half2*>(&uv);
    uint4 ov;
    __half2* op = reinterpret_cast<__half2*>(&ov);
    #pragma unroll
    for (int k = 0; k < 4; k++) {
        float2 g = __half22float2(gp[k]);
        float2 u = __half22float2(up[k]);
        float h0 = g.x * u.x * (1.0f / (1.0f + __expf(-u.x)));
        float h1 = g.y * u.y * (1.0f / (1.0f + __expf(-u.y)));
        op[k] = __floats2half2_rn(h0, h1);
    }
    *reinterpret_cast<uint4*>(h + (size_t)r * INTER + c8 * 8) = ov;
}

// ---------------------------------------------------------------------------
// Pipelined fp16 GEMM:  C[BM x BN] = A[BM x K] * B[BN x K]^T + bias
//   HALF_OUT=true : store fp16 (gateup buffer), false: fp32 (final out)
// 256 threads = 8 warps (4M x 2N); warp tile 32 x 48 (NF=6 n8 frags).
// Smem rows 128B, 16B units XOR-swizzled by (row&7). Register double-buffered
// fragments, 3-stage cp.async, 2 CTAs/SM.
// ---------------------------------------------------------------------------
template <bool HALF_OUT>
__global__ void __launch_bounds__(256, 2)
gemm_f16(const __half* __restrict__ A, const __half* __restrict__ B,
         const float* __restrict__ bias,
         __half* __restrict__ oH, float* __restrict__ oF, int ldo) {
    extern __shared__ __align__(128) char smem[];
    const uint32_t sb0 = smem_u32(smem);
    const int tid = threadIdx.x;
    const int l   = tid & 31;
    const int wid = tid >> 5;          // 0..7
    const int wm  = wid >> 1;          // 0..3
    const int wn  = wid & 1;           // 0..1
    const int mBase = blockIdx.x * BM;
    const int nBase = blockIdx.y * BN;

    auto load_stage = [&](int kt, int slot) {
        const uint32_t sb = sb0 + slot * STAGE;
        const int kc = kt * BK;
        #pragma unroll
        for (int k = 0; k < 4; k++) {                     // A: 1024 chunks
            int idx = tid + k * 256;
            int row = idx >> 3, u = idx & 7;
            cp16(sb + row * 128 + ((u ^ (row & 7)) << 4),
                 A + (size_t)(mBase + row) * HID + kc + u * 8);
        }
        #pragma unroll
        for (int k = 0; k < 3; k++) {                     // B: 768 chunks
            int idx = tid + k * 256;
            int row = idx >> 3, u = idx & 7;
            cp16(sb + OFF_B + row * 128 + ((u ^ (row & 7)) << 4),
                 B + (size_t)(nBase + row) * HID + kc + u * 8);
        }
    };

    const int l7  = l & 7;
    const int lhi = l >> 4;
    const int le  = l & 15;
    const int q   = l >> 3;
    const int aRow0 = wm * 32 + le;
    const int bRowO = wn * 48 + ((q >> 1) << 3) + l7;
    const int bUnit = q & 1;

    auto loadA = [&](uint32_t af[2][4], uint32_t sA, int ks) {
        #pragma unroll
        for (int i = 0; i < 2; i++)
            ldsm4(af[i], sA + (uint32_t)(aRow0 + i * 16) * 128 +
                           (uint32_t)(((ks * 2 + lhi) ^ l7) << 4));
    };
    auto loadB = [&](uint32_t bf[3][4], uint32_t sB, int ks) {
        #pragma unroll
        for (int p = 0; p < 3; p++)
            ldsm4(bf[p], sB + (uint32_t)(bRowO + p * 16) * 128 +
                           (uint32_t)(((ks * 2 + bUnit) ^ l7) << 4));
    };

    float acc[2][6][4] = {};
    uint32_t af[2][2][4], bf[2][3][4];

    #pragma unroll
    for (int s = 0; s < STAGES - 1; s++) {                // prologue
        load_stage(s, s);
        CP_COMMIT();
    }

    for (int kt = 0; kt < KIT; kt++) {
        CP_WAIT_1();
        __syncthreads();

        const int nk = kt + STAGES - 1;
        if (nk < KIT) load_stage(nk, nk % STAGES);
        CP_COMMIT();

        const uint32_t sA = sb0 + (kt % STAGES) * STAGE;
        const uint32_t sB = sA + OFF_B;

        loadA(af[0], sA, 0);
        loadB(bf[0], sB, 0);
        #pragma unroll
        for (int ks = 0; ks < 4; ks++) {
            const int cur = ks & 1, nxt = cur ^ 1;
            if (ks < 3) {
                loadA(af[nxt], sA, ks + 1);
                loadB(bf[nxt], sB, ks + 1);
            }
            #pragma unroll
            for (int i = 0; i < 2; i++)
                #pragma unroll
                for (int p = 0; p < 3; p++) {
                    mma16816(acc[i][2 * p],     af[cur][i], &bf[cur][p][0]);
                    mma16816(acc[i][2 * p + 1], af[cur][i], &bf[cur][p][2]);
                }
        }
    }

    // ------------------------------- epilogue -------------------------------
    const int r00 = mBase + wm * 32 + (l >> 2);
    const int cB  = nBase + wn * 48 + 2 * (l & 3);

    #pragma unroll
    for (int i = 0; i < 2; i++)
        #pragma unroll
        for (int j = 0; j < 6; j++) {
            const int c = cB + j * 8;
            const float b0 = __ldg(bias + c), b1 = __ldg(bias + c + 1);
            #pragma unroll
            for (int hh = 0; hh < 2; hh++) {
                const int r = r00 + i * 16 + hh * 8;
                const float v0 = acc[i][j][2 * hh]     + b0;
                const float v1 = acc[i][j][2 * hh + 1] + b1;
                if constexpr (HALF_OUT) {
                    *reinterpret_cast<__half2*>(oH + (size_t)r * ldo + c) =
                        __floats2half2_rn(v0, v1);
                } else {
                    *reinterpret_cast<float2*>(oF + (size_t)r * ldo + c) =
                        make_float2(v0, v1);
                }
            }
        }
}

// ---------------------------------------------------------------------------
// Host
// ---------------------------------------------------------------------------
extern "C" void kernel_launch(void* const* d_in, const int* in_sizes, int n_in,
                              void* d_out, int out_size) {
    const float* x  = (const float*)d_in[0];   // hidden_states (4096, 2880)
    const float* w1 = (const float*)d_in[3];   // gate_up_w (5760, 2880)
    const float* b1 = (const float*)d_in[4];   // gate_up_b (5760,)
    const float* w2 = (const float*)d_in[5];   // down_w (2880, 2880)
    const float* b2 = (const float*)d_in[6];   // down_b (2880,)
    float* out = (float*)d_out;                // (4096, 2880) fp32

    void *px, *pw1, *pw2, *pgu, *ph;
    cudaGetSymbolAddress(&px,  g_xh);
    cudaGetSymbolAddress(&pw1, g_w1h);
    cudaGetSymbolAddress(&pw2, g_w2h);
    cudaGetSymbolAddress(&pgu, g_gu);
    cudaGetSymbolAddress(&ph,  g_hh);

    // fp32 -> fp16
    {
        int n4 = (SEQ * HID) / 4;
        cvt_kernel<<<(n4 + 255) / 256, 256>>>((const float4*)x,  (uint2*)px,  n4);
        n4 = (NGU * HID) / 4;
        cvt_kernel<<<(n4 + 255) / 256, 256>>>((const float4*)w1, (uint2*)pw1, n4);
        n4 = (HID * INTER) / 4;
        cvt_kernel<<<(n4 + 255) / 256, 256>>>((const float4*)w2, (uint2*)pw2, n4);
    }

    cudaFuncSetAttribute(gemm_f16<true>,
                         cudaFuncAttributeMaxDynamicSharedMemorySize, SMEM_SZ);
    cudaFuncSetAttribute(gemm_f16<false>,
                         cudaFuncAttributeMaxDynamicSharedMemorySize, SMEM_SZ);

    // GEMM1: gateup = x @ W1^T + b1   (fp16, 4096 x 5760)
    gemm_f16<true><<<dim3(SEQ / BM, NGU / BN), 256, SMEM_SZ>>>(
        (const __half*)px, (const __half*)pw1, b1, (__half*)pgu, nullptr, NGU);

    // SiLU: h = gate * silu(up)   (fp16, 4096 x 2880)
    {
        int n8 = SEQ * INTER / 8;
        silu_kernel<<<(n8 + 255) / 256, 256>>>((const __half*)pgu, (__half*)ph);
    }

    // GEMM2: out = h @ W2^T + b2   (fp32, 4096 x 2880)
    gemm_f16<false><<<dim3(SEQ / BM, INTER / BN), 256, SMEM_SZ>>>(
        (const __half*)ph, (const __half*)pw2, b2, nullptr, out, HID);
}

// round 4
// speedup vs baseline: 1.2409x; 1.0575x over previous
#include <cuda_runtime.h>
#include <cuda_fp16.h>
#include <cstdint>

// ============================================================================
// GptOssMoEExperts: router collapses to identity (softmax over top-k sums to 1
// and the expert MLP is shared), so
//   out = ((x@Wg^T+bg) * silu(x@Wu^T+bu)) @ W2^T + b2
// cvt fp32->fp16, GEMM1 (x@W1^T+b1 -> gateup fp16, 5760 cols), SiLU, GEMM2.
// mma.sync m16n8k16 fp16->fp32, cp.async 3-stage pipeline.
// This round: warp tile 64x48 (was 32x48), 4 warps/CTA x 2 CTA/SM —
// load/MMA ratio 7/24 (was 5/12), no 128-reg cap, more ILP per warp.
// ============================================================================

#define SEQ   4096
#define HID   2880
#define INTER 2880
#define NGU   (2 * INTER)   // 5760

static constexpr int BM     = 128;
static constexpr int BN     = 96;
static constexpr int BK     = 64;            // fp16 elems -> 128B rows
static constexpr int KIT    = HID / BK;      // 45
static constexpr int STAGES = 3;
static constexpr int OFF_B  = BM * 128;               // 16384
static constexpr int STAGE  = OFF_B + BN * 128;       // 28672
static constexpr int SMEM_SZ = STAGES * STAGE;        // 86016 (x2 CTA = 172KB/SM)

// ---------------------------------------------------------------------------
// Scratch (__device__ globals = sanctioned allocation-free scratch)
// ---------------------------------------------------------------------------
__device__ __align__(128) __half g_xh [(size_t)SEQ * HID];
__device__ __align__(128) __half g_w1h[(size_t)NGU * HID];
__device__ __align__(128) __half g_w2h[(size_t)HID * INTER];
__device__ __align__(128) __half g_gu [(size_t)SEQ * NGU];
__device__ __align__(128) __half g_hh [(size_t)SEQ * INTER];

// ---------------------------------------------------------------------------
// PTX helpers
// ---------------------------------------------------------------------------
__device__ __forceinline__ uint32_t smem_u32(const void* p) {
    uint32_t a;
    asm("{ .reg .u64 t; cvta.to.shared.u64 t, %1; cvt.u32.u64 %0, t; }" : "=r"(a) : "l"(p));
    return a;
}
__device__ __forceinline__ void ldsm4(uint32_t* r, uint32_t a) {
    asm volatile("ldmatrix.sync.aligned.m8n8.x4.shared.b16 {%0,%1,%2,%3}, [%4];"
                 : "=r"(r[0]), "=r"(r[1]), "=r"(r[2]), "=r"(r[3]) : "r"(a));
}
__device__ __forceinline__ void mma16816(float* d, const uint32_t* a, const uint32_t* b) {
    asm volatile(
        "mma.sync.aligned.m16n8k16.row.col.f32.f16.f16.f32 "
        "{%0,%1,%2,%3}, {%4,%5,%6,%7}, {%8,%9}, {%0,%1,%2,%3};"
        : "+f"(d[0]), "+f"(d[1]), "+f"(d[2]), "+f"(d[3])
        : "r"(a[0]), "r"(a[1]), "r"(a[2]), "r"(a[3]), "r"(b[0]), "r"(b[1]));
}
__device__ __forceinline__ void cp16(uint32_t s, const void* g) {
    asm volatile("cp.async.cg.shared.global [%0], [%1], 16;" :: "r"(s), "l"(g) : "memory");
}
#define CP_COMMIT()  asm volatile("cp.async.commit_group;" ::: "memory")
#define CP_WAIT_1()  asm volatile("cp.async.wait_group 1;"  ::: "memory")

// ---------------------------------------------------------------------------
// fp32 -> fp16 conversion (vectorized)
// ---------------------------------------------------------------------------
__global__ void cvt_kernel(const float4* __restrict__ src, uint2* __restrict__ dst, int n4) {
    int i = blockIdx.x * blockDim.x + threadIdx.x;
    if (i >= n4) return;
    float4 v = src[i];
    __half2 a = __floats2half2_rn(v.x, v.y);
    __half2 b = __floats2half2_rn(v.z, v.w);
    uint2 o;
    o.x = *reinterpret_cast<uint32_t*>(&a);
    o.y = *reinterpret_cast<uint32_t*>(&b);
    dst[i] = o;
}

// ---------------------------------------------------------------------------
// Elementwise SiLU-mul: h[r,c] = gu[r,c] * silu(gu[r,INTER+c]), 8 elems/thread
// ---------------------------------------------------------------------------
__global__ void silu_kernel(const __half* __restrict__ gu, __half* __restrict__ h) {
    const int i = blockIdx.x * blockDim.x + threadIdx.x;
    const int n8 = SEQ * INTER / 8;
    if (i >= n8) return;
    const int r  = i / (INTER / 8);
    const int c8 = i % (INTER / 8);
    const uint4 gv = *reinterpret_cast<const uint4*>(gu + (size_t)r * NGU + c8 * 8);
    const uint4 uv = *reinterpret_cast<const uint4*>(gu + (size_t)r * NGU + INTER + c8 * 8);
    const __half2* gp = reinterpret_cast<const __half2*>(&gv);
    const __half2* up = reinterpret_cast<const __half2*>(&uv);
    uint4 ov;
    __half2* op = reinterpret_cast<__half2*>(&ov);
    #pragma unroll
    for (int k = 0; k < 4; k++) {
        float2 g = __half22float2(gp[k]);
        float2 u = __half22float2(up[k]);
        float h0 = g.x * u.x * (1.0f / (1.0f + __expf(-u.x)));
        float h1 = g.y * u.y * (1.0f / (1.0f + __expf(-u.y)));
        op[k] = __floats2half2_rn(h0, h1);
    }
    *reinterpret_cast<uint4*>(h + (size_t)r * INTER + c8 * 8) = ov;
}

// ---------------------------------------------------------------------------
// Pipelined fp16 GEMM:  C[BM x BN] = A[BM x K] * B[BN x K]^T + bias
//   HALF_OUT=true : store fp16 (gateup buffer), false: fp32 (final out)
// 128 threads = 4 warps (2M x 2N); warp tile 64 x 48 (4 m16 x 6 n8 frags).
// Per k16: 4 A-ldsm4 + 3 B-ldsm4, 24 MMAs. Register double-buffered frags.
// Smem rows 128B, 16B units XOR-swizzled by (row&7). 2 CTAs/SM.
// ---------------------------------------------------------------------------
template <bool HALF_OUT>
__global__ void __launch_bounds__(128, 2)
gemm_f16(const __half* __restrict__ A, const __half* __restrict__ B,
         const float* __restrict__ bias,
         __half* __restrict__ oH, float* __restrict__ oF, int ldo) {
    extern __shared__ __align__(128) char smem[];
    const uint32_t sb0 = smem_u32(smem);
    const int tid = threadIdx.x;
    const int l   = tid & 31;
    const int wid = tid >> 5;          // 0..3
    const int wm  = wid >> 1;          // 0..1
    const int wn  = wid & 1;           // 0..1
    const int mBase = blockIdx.x * BM;
    const int nBase = blockIdx.y * BN;

    auto load_stage = [&](int kt, int slot) {
        const uint32_t sb = sb0 + slot * STAGE;
        const int kc = kt * BK;
        #pragma unroll
        for (int k = 0; k < 8; k++) {                     // A: 1024 chunks
            int idx = tid + k * 128;
            int row = idx >> 3, u = idx & 7;
            cp16(sb + row * 128 + ((u ^ (row & 7)) << 4),
                 A + (size_t)(mBase + row) * HID + kc + u * 8);
        }
        #pragma unroll
        for (int k = 0; k < 6; k++) {                     // B: 768 chunks
            int idx = tid + k * 128;
            int row = idx >> 3, u = idx & 7;
            cp16(sb + OFF_B + row * 128 + ((u ^ (row & 7)) << 4),
                 B + (size_t)(nBase + row) * HID + kc + u * 8);
        }
    };

    const int l7  = l & 7;
    const int lhi = l >> 4;
    const int le  = l & 15;
    const int q   = l >> 3;
    const int aRow0 = wm * 64 + le;
    const int bRowO = wn * 48 + ((q >> 1) << 3) + l7;
    const int bUnit = q & 1;

    auto loadA = [&](uint32_t af[4][4], uint32_t sA, int ks) {
        #pragma unroll
        for (int i = 0; i < 4; i++)
            ldsm4(af[i], sA + (uint32_t)(aRow0 + i * 16) * 128 +
                           (uint32_t)(((ks * 2 + lhi) ^ l7) << 4));
    };
    auto loadB = [&](uint32_t bf[3][4], uint32_t sB, int ks) {
        #pragma unroll
        for (int p = 0; p < 3; p++)
            ldsm4(bf[p], sB + (uint32_t)(bRowO + p * 16) * 128 +
                           (uint32_t)(((ks * 2 + bUnit) ^ l7) << 4));
    };

    float acc[4][6][4] = {};
    uint32_t af[2][4][4], bf[2][3][4];

    #pragma unroll
    for (int s = 0; s < STAGES - 1; s++) {                // prologue
        load_stage(s, s);
        CP_COMMIT();
    }

    for (int kt = 0; kt < KIT; kt++) {
        CP_WAIT_1();
        __syncthreads();

        const int nk = kt + STAGES - 1;
        if (nk < KIT) load_stage(nk, nk % STAGES);
        CP_COMMIT();

        const uint32_t sA = sb0 + (kt % STAGES) * STAGE;
        const uint32_t sB = sA + OFF_B;

        loadA(af[0], sA, 0);
        loadB(bf[0], sB, 0);
        #pragma unroll
        for (int ks = 0; ks < 4; ks++) {
            const int cur = ks & 1, nxt = cur ^ 1;
            if (ks < 3) {
                loadA(af[nxt], sA, ks + 1);
                loadB(bf[nxt], sB, ks + 1);
            }
            #pragma unroll
            for (int i = 0; i < 4; i++)
                #pragma unroll
                for (int p = 0; p < 3; p++) {
                    mma16816(acc[i][2 * p],     af[cur][i], &bf[cur][p][0]);
                    mma16816(acc[i][2 * p + 1], af[cur][i], &bf[cur][p][2]);
                }
        }
    }

    // ------------------------------- epilogue -------------------------------
    const int r00 = mBase + wm * 64 + (l >> 2);
    const int cB  = nBase + wn * 48 + 2 * (l & 3);

    #pragma unroll
    for (int i = 0; i < 4; i++)
        #pragma unroll
        for (int j = 0; j < 6; j++) {
            const int c = cB + j * 8;
            const float b0 = __ldg(bias + c), b1 = __ldg(bias + c + 1);
            #pragma unroll
            for (int hh = 0; hh < 2; hh++) {
                const int r = r00 + i * 16 + hh * 8;
                const float v0 = acc[i][j][2 * hh]     + b0;
                const float v1 = acc[i][j][2 * hh + 1] + b1;
                if constexpr (HALF_OUT) {
                    *reinterpret_cast<__half2*>(oH + (size_t)r * ldo + c) =
                        __floats2half2_rn(v0, v1);
                } else {
                    *reinterpret_cast<float2*>(oF + (size_t)r * ldo + c) =
                        make_float2(v0, v1);
                }
            }
        }
}

// ---------------------------------------------------------------------------
// Host
// ---------------------------------------------------------------------------
extern "C" void kernel_launch(void* const* d_in, const int* in_sizes, int n_in,
                              void* d_out, int out_size) {
    const float* x  = (const float*)d_in[0];   // hidden_states (4096, 2880)
    const float* w1 = (const float*)d_in[3];   // gate_up_w (5760, 2880)
    const float* b1 = (const float*)d_in[4];   // gate_up_b (5760,)
    const float* w2 = (const float*)d_in[5];   // down_w (2880, 2880)
    const float* b2 = (const float*)d_in[6];   // down_b (2880,)
    float* out = (float*)d_out;                // (4096, 2880) fp32

    void *px, *pw1, *pw2, *pgu, *ph;
    cudaGetSymbolAddress(&px,  g_xh);
    cudaGetSymbolAddress(&pw1, g_w1h);
    cudaGetSymbolAddress(&pw2, g_w2h);
    cudaGetSymbolAddress(&pgu, g_gu);
    cudaGetSymbolAddress(&ph,  g_hh);

    // fp32 -> fp16
    {
        int n4 = (SEQ * HID) / 4;
        cvt_kernel<<<(n4 + 255) / 256, 256>>>((const float4*)x,  (uint2*)px,  n4);
        n4 = (NGU * HID) / 4;
        cvt_kernel<<<(n4 + 255) / 256, 256>>>((const float4*)w1, (uint2*)pw1, n4);
        n4 = (HID * INTER) / 4;
        cvt_kernel<<<(n4 + 255) / 256, 256>>>((const float4*)w2, (uint2*)pw2, n4);
    }

    cudaFuncSetAttribute(gemm_f16<true>,
                         cudaFuncAttributeMaxDynamicSharedMemorySize, SMEM_SZ);
    cudaFuncSetAttribute(gemm_f16<false>,
                         cudaFuncAttributeMaxDynamicSharedMemorySize, SMEM_SZ);

    // GEMM1: gateup = x @ W1^T + b1   (fp16, 4096 x 5760)
    gemm_f16<true><<<dim3(SEQ / BM, NGU / BN), 128, SMEM_SZ>>>(
        (const __half*)px, (const __half*)pw1, b1, (__half*)pgu, nullptr, NGU);

    // SiLU: h = gate * silu(up)   (fp16, 4096 x 2880)
    {
        int n8 = SEQ * INTER / 8;
        silu_kernel<<<(n8 + 255) / 256, 256>>>((const __half*)pgu, (__half*)ph);
    }

    // GEMM2: out = h @ W2^T + b2   (fp32, 4096 x 2880)
    gemm_f16<false><<<dim3(SEQ / BM, INTER / BN), 128, SMEM_SZ>>>(
        (const __half*)ph, (const __half*)pw2, b2, nullptr, out, HID);
}